// round 16
// baseline (speedup 1.0000x reference)
#include <cuda_runtime.h>
#include <cuda_fp16.h>
#include <math.h>
#include <stdint.h>

// Problem constants
#define BATCH 2
#define SEQ   2048
#define DMODEL 512
#define NHEAD 8
#define DHEAD 64
#define NTOK  (BATCH*SEQ)          // 4096
#define NQK   1024
#define NFEAT 1536
#define CHUNK 128
#define NCHUNK (SEQ/CHUNK)         // 16
#define BHEADS (BATCH*NHEAD)       // 16

// Scratch (device globals)
__device__ __half g_qh[BHEADS*SEQ*DHEAD];
__device__ __half g_kh[BHEADS*SEQ*DHEAD];
__device__ __half g_vh[BHEADS*SEQ*DHEAD];
__device__ __half g_ctxh[NTOK*DMODEL];
__device__ __half g_kv_preh[BHEADS*NCHUNK*DHEAD*DHEAD];
__device__ float  g_z_pre[BHEADS*NCHUNK*DHEAD];
// fp16 copies of inputs
__device__ __half g_xh[NTOK*DMODEL];
__device__ __half g_wqkh[NQK*DMODEL];
__device__ __half g_wvh[DMODEL*DMODEL];
__device__ __half g_woh[DMODEL*DMODEL];

// ---------------------------------------------------------------------------
// Helpers
// ---------------------------------------------------------------------------
__device__ __forceinline__ uint32_t smem_u32(const void* p) {
    return (uint32_t)__cvta_generic_to_shared(p);
}
__device__ __forceinline__ void cp_async16(uint32_t s, const void* g) {
    asm volatile("cp.async.cg.shared.global [%0], [%1], 16;\n" :: "r"(s), "l"(g));
}
__device__ __forceinline__ void cp_commit() { asm volatile("cp.async.commit_group;\n"); }
__device__ __forceinline__ void cp_wait1()  { asm volatile("cp.async.wait_group 1;\n"); }
__device__ __forceinline__ void cp_wait0()  { asm volatile("cp.async.wait_group 0;\n"); }

// PDL primitives (sm_90+ base PTX)
#define GRID_DEP_WAIT()   asm volatile("griddepcontrol.wait;" ::: "memory")
#define GRID_DEP_LAUNCH() asm volatile("griddepcontrol.launch_dependents;" ::: "memory")

__device__ __forceinline__ void mma_f16(float c[4],
    uint32_t a0, uint32_t a1, uint32_t a2, uint32_t a3,
    uint32_t b0, uint32_t b1)
{
    asm volatile(
        "mma.sync.aligned.m16n8k16.row.col.f32.f16.f16.f32 "
        "{%0,%1,%2,%3}, {%4,%5,%6,%7}, {%8,%9}, {%0,%1,%2,%3};"
        : "+f"(c[0]), "+f"(c[1]), "+f"(c[2]), "+f"(c[3])
        : "r"(a0), "r"(a1), "r"(a2), "r"(a3), "r"(b0), "r"(b1));
}
__device__ __forceinline__ void ldsm_x4(uint32_t& r0, uint32_t& r1,
                                        uint32_t& r2, uint32_t& r3, uint32_t addr)
{
    asm volatile("ldmatrix.sync.aligned.m8n8.x4.shared.b16 {%0,%1,%2,%3}, [%4];"
                 : "=r"(r0), "=r"(r1), "=r"(r2), "=r"(r3) : "r"(addr));
}
__device__ __forceinline__ void ldsm_x4t(uint32_t& r0, uint32_t& r1,
                                         uint32_t& r2, uint32_t& r3, uint32_t addr)
{
    asm volatile("ldmatrix.sync.aligned.m8n8.x4.trans.shared.b16 {%0,%1,%2,%3}, [%4];"
                 : "=r"(r0), "=r"(r1), "=r"(r2), "=r"(r3) : "r"(addr));
}
__device__ __forceinline__ void ldsm_x2t(uint32_t& r0, uint32_t& r1, uint32_t addr)
{
    asm volatile("ldmatrix.sync.aligned.m8n8.x2.trans.shared.b16 {%0,%1}, [%2];"
                 : "=r"(r0), "=r"(r1) : "r"(addr));
}
__device__ __forceinline__ uint32_t pack_h2(float a, float b) {
    half2 h = __floats2half2_rn(a, b);
    return *(uint32_t*)&h;
}

// ---------------------------------------------------------------------------
// Kernel 0: convert inputs fp32 -> fp16 (rn)
// ---------------------------------------------------------------------------
#define N8_X   (NTOK*DMODEL/8)
#define N8_WQK (NQK*DMODEL/8)
#define N8_WV  (DMODEL*DMODEL/8)
#define N8_WO  (DMODEL*DMODEL/8)
#define N8_TOT (N8_X+N8_WQK+N8_WV+N8_WO)

__global__ __launch_bounds__(256) void conv_kernel(
    const float4* __restrict__ x, const float4* __restrict__ wqk,
    const float4* __restrict__ wv, const float4* __restrict__ wo)
{
    int idx = blockIdx.x * 256 + threadIdx.x;
    const float4* src; __half* dst; int off;
    if (idx < N8_X)                    { src = x;   dst = g_xh;   off = idx; }
    else if (idx < N8_X+N8_WQK)        { src = wqk; dst = g_wqkh; off = idx - N8_X; }
    else if (idx < N8_X+N8_WQK+N8_WV)  { src = wv;  dst = g_wvh;  off = idx - N8_X - N8_WQK; }
    else                               { src = wo;  dst = g_woh;  off = idx - N8_X - N8_WQK - N8_WV; }
    float4 a = src[2*off];
    float4 b = src[2*off+1];
    half2 h[4];
    h[0] = __floats2half2_rn(a.x, a.y);
    h[1] = __floats2half2_rn(a.z, a.w);
    h[2] = __floats2half2_rn(b.x, b.y);
    h[3] = __floats2half2_rn(b.z, b.w);
    *(uint4*)(dst + (size_t)off*8) = *(uint4*)h;
    GRID_DEP_LAUNCH();
}

// ---------------------------------------------------------------------------
// FP16 GEMM core: k-tile 64, warps of 64x32, 2-stage pipe.
// ---------------------------------------------------------------------------
#define KTH 64
#define NKTH (DMODEL/KTH)            // 8
#define ASTRH 72
#define TILE_HALFS (128*ASTRH)
#define NSTAGE 2
#define GEMM_SMEM_BYTES (NSTAGE*2*TILE_HALFS*2)   // 73728

__device__ __forceinline__ void gemm_tile_f16(
    const __half* A, const __half* B,
    int warp_m, int warp_n, int lane, float c[4][4][4])
{
    const uint32_t Ab = smem_u32(A);
    const uint32_t Bb = smem_u32(B);
    const int arow = warp_m + (lane & 15);
    const int acol = ((lane >> 4) & 1) * 8;
    const int bg   = lane >> 3;
    const int brow = warp_n + (bg >> 1) * 8 + (lane & 7);
    const int bcol = (bg & 1) * 8;
#pragma unroll
    for (int kk = 0; kk < KTH; kk += 16) {
        uint32_t af[4][4];
        uint32_t bf[4][2];
#pragma unroll
        for (int mt = 0; mt < 4; mt++)
            ldsm_x4(af[mt][0], af[mt][1], af[mt][2], af[mt][3],
                    Ab + (uint32_t)(((arow + mt*16)*ASTRH + kk + acol)*2));
#pragma unroll
        for (int p = 0; p < 2; p++)
            ldsm_x4(bf[2*p][0], bf[2*p][1], bf[2*p+1][0], bf[2*p+1][1],
                    Bb + (uint32_t)(((brow + p*16)*ASTRH + kk + bcol)*2));
#pragma unroll
        for (int mt = 0; mt < 4; mt++)
#pragma unroll
            for (int nt = 0; nt < 4; nt++)
                mma_f16(c[mt][nt], af[mt][0], af[mt][1], af[mt][2], af[mt][3],
                        bf[nt][0], bf[nt][1]);
    }
}

// ---------------------------------------------------------------------------
// Kernel 1: fused QKV GEMM (fp16 HMMA), 128x128 tiles
// ---------------------------------------------------------------------------
__global__ __launch_bounds__(256, 2) void qkv_f16_gemm(
    const float* __restrict__ bqk, const float* __restrict__ bv)
{
    extern __shared__ __half smh[];
    __half* As = smh;
    __half* Bs = smh + NSTAGE*TILE_HALFS;

    GRID_DEP_WAIT();

    const int n0 = blockIdx.x * 128;
    const int m0 = blockIdx.y * 128;
    const int tid = threadIdx.x;
    const int wid = tid >> 5;
    const int lane = tid & 31;
    const int warp_m = (wid & 1) * 64;
    const int warp_n = (wid >> 1) * 32;

    float c[4][4][4];
#pragma unroll
    for (int mt = 0; mt < 4; mt++)
#pragma unroll
        for (int nt = 0; nt < 4; nt++)
#pragma unroll
            for (int i = 0; i < 4; i++) c[mt][nt][i] = 0.f;

    auto load_stage = [&](int kt, int stage) {
        const int k0 = kt * KTH;
        __half* Ad = As + stage * TILE_HALFS;
        __half* Bd = Bs + stage * TILE_HALFS;
#pragma unroll
        for (int it = 0; it < 8; it++) {
            int i = tid + it*256;
            int reg = i >> 10;
            int row = (i & 1023) >> 3;
            int seg = (i & 7) * 8;
            if (reg == 0) {
                cp_async16(smem_u32(Ad + row*ASTRH + seg),
                           g_xh + (size_t)(m0 + row)*DMODEL + k0 + seg);
            } else {
                int n = n0 + row;
                const __half* wrow = (n < NQK) ? (g_wqkh + (size_t)n*DMODEL)
                                               : (g_wvh + (size_t)(n-NQK)*DMODEL);
                cp_async16(smem_u32(Bd + row*ASTRH + seg), wrow + k0 + seg);
            }
        }
        cp_commit();
    };

    load_stage(0, 0);
    load_stage(1, 1);
    for (int kt = 0; kt < NKTH; kt++) {
        if (kt < NKTH - 1) cp_wait1(); else cp_wait0();
        __syncthreads();
        int st = kt & 1;
        gemm_tile_f16(As + st*TILE_HALFS, Bs + st*TILE_HALFS,
                      warp_m, warp_n, lane, c);
        if (kt + 2 < NKTH) {
            __syncthreads();
            load_stage(kt + 2, st);
        }
    }

    const int lq = lane >> 2;
    const int lc = (lane & 3) * 2;
#pragma unroll
    for (int mt = 0; mt < 4; mt++) {
#pragma unroll
        for (int rv = 0; rv < 2; rv++) {
            int m = m0 + warp_m + mt*16 + lq + rv*8;
            int bb = m / SEQ;
            int ss = m % SEQ;
#pragma unroll
            for (int nt = 0; nt < 4; nt++) {
                int nf = n0 + warp_n + nt*8 + lc;
                float v0 = c[mt][nt][rv*2+0];
                float v1 = c[mt][nt][rv*2+1];
                if (nf < NQK) {
                    v0 += bqk[nf];   v1 += bqk[nf+1];
                    v0 = (v0 > 0.f) ? (v0 + 1.f) : expf(v0);
                    v1 = (v1 > 0.f) ? (v1 + 1.f) : expf(v1);
                } else {
                    v0 += bv[nf-NQK]; v1 += bv[nf-NQK+1];
                }
                __half* dst;
                if (nf < DMODEL) {
                    int h = nf / DHEAD, d = nf % DHEAD;
                    dst = g_qh + (((size_t)(bb*NHEAD + h))*SEQ + ss)*DHEAD + d;
                } else if (nf < NQK) {
                    int nn = nf - DMODEL;
                    int h = nn / DHEAD, d = nn % DHEAD;
                    dst = g_kh + (((size_t)(bb*NHEAD + h))*SEQ + ss)*DHEAD + d;
                } else {
                    int nn = nf - NQK;
                    int h = nn / DHEAD, d = nn % DHEAD;
                    dst = g_vh + (((size_t)(bb*NHEAD + h))*SEQ + ss)*DHEAD + d;
                }
                *(half2*)dst = __floats2half2_rn(v0, v1);
            }
        }
    }
    GRID_DEP_LAUNCH();
}

// ---------------------------------------------------------------------------
// Kernel 2: chunk state + exclusive prefix via tensor cores.
// z-sum via tensor core (constant ones-column block at V cols 32-39).
// ---------------------------------------------------------------------------
#define CS_KSTR 72
#define CS_VSTR 40
#define CS_KT (128*CS_KSTR)
#define CS_VT (128*CS_VSTR)
#define CS_SMEM_BYTES ((2*CS_KT + 2*CS_VT)*2)   // 57344

__global__ __launch_bounds__(256) void chunk_state_kernel()
{
    extern __shared__ __half smh[];
    __half* ks = smh;
    __half* vs = smh + 2*CS_KT;

    GRID_DEP_WAIT();

    const int bh  = blockIdx.x;
    const int slv = blockIdx.y;
    const int tid = threadIdx.x;
    const int wid = tid >> 5;
    const int lane = tid & 31;
    const int d0 = (wid & 3) * 16;
    const int n0 = (wid >> 2) * 16;
    const int lq = lane >> 2;
    const int lr = lane & 3;
    const bool do_z = (slv == 0) && ((wid >> 2) == 0);

    const __half* kp = g_kh + (size_t)bh*SEQ*DHEAD;
    const __half* vp = g_vh + (size_t)bh*SEQ*DHEAD + slv*32;

    // init constant z-columns (cols 32..39) in both V stages: col32=1, rest 0
    {
        int row = tid & 127;
        int st2 = tid >> 7;
        __half* vrow = vs + st2*CS_VT + row*CS_VSTR + 32;
        vrow[0] = __float2half(1.f);
#pragma unroll
        for (int cc = 1; cc < 8; cc++) vrow[cc] = __float2half(0.f);
    }

    auto load_stage = [&](int c, int st) {
        const __half* kc = kp + (size_t)c*CHUNK*DHEAD;
        const __half* vc = vp + (size_t)c*CHUNK*DHEAD;
        __half* kd = ks + st*CS_KT;
        __half* vd = vs + st*CS_VT;
#pragma unroll
        for (int i = 0; i < 6; i++) {
            int idx = tid + i*256;
            if (idx < 1024) {
                int row = idx >> 3, seg = (idx & 7) * 8;
                cp_async16(smem_u32(kd + row*CS_KSTR + seg), kc + (size_t)row*DHEAD + seg);
            } else {
                int j = idx - 1024;
                int row = j >> 2, seg = (j & 3) * 8;
                cp_async16(smem_u32(vd + row*CS_VSTR + seg), vc + (size_t)row*DHEAD + seg);
            }
        }
        cp_commit();
    };

    float acc[2][4];
#pragma unroll
    for (int nt = 0; nt < 2; nt++)
#pragma unroll
        for (int i = 0; i < 4; i++) acc[nt][i] = 0.f;
    float zrun0 = 0.f, zrun1 = 0.f;

    const int sA = (lane & 7) + ((lane >> 4) & 1) * 8;
    const int dA = ((lane >> 3) & 1) * 8;
    const int sB = (lane & 7) + ((lane >> 3) & 1) * 8;
    const int nB = ((lane >> 4) & 1) * 8;

    load_stage(0, 0);
    load_stage(1, 1);

    for (int c = 0; c < NCHUNK; c++) {
        // publish exclusive-prefix state for chunk c
        {
            __half* kvo = g_kv_preh + ((size_t)(bh*NCHUNK + c))*(DHEAD*DHEAD);
            int col = slv*32 + n0 + 2*lr;
#pragma unroll
            for (int nt = 0; nt < 2; nt++) {
                *(half2*)(kvo + (d0 + lq)*DHEAD + col + nt*8)
                    = __floats2half2_rn(acc[nt][0], acc[nt][1]);
                *(half2*)(kvo + (d0 + lq + 8)*DHEAD + col + nt*8)
                    = __floats2half2_rn(acc[nt][2], acc[nt][3]);
            }
            if (do_z && lr == 0) {
                g_z_pre[(size_t)(bh*NCHUNK + c)*DHEAD + d0 + lq]     = zrun0;
                g_z_pre[(size_t)(bh*NCHUNK + c)*DHEAD + d0 + lq + 8] = zrun1;
            }
        }

        if (c < NCHUNK - 1) cp_wait1(); else cp_wait0();
        __syncthreads();

        const int st = c & 1;
        const uint32_t ksb = smem_u32(ks + st*CS_KT);
        const uint32_t vsb = smem_u32(vs + st*CS_VT);
        float zfrag[4] = {0.f, 0.f, 0.f, 0.f};
#pragma unroll
        for (int s0 = 0; s0 < 128; s0 += 16) {
            uint32_t a0, a1, a2, a3, b0, b1, b2, b3;
            ldsm_x4t(a0, a1, a2, a3,
                     ksb + (uint32_t)(((s0 + sA)*CS_KSTR + d0 + dA)*2));
            ldsm_x4t(b0, b1, b2, b3,
                     vsb + (uint32_t)(((s0 + sB)*CS_VSTR + n0 + nB)*2));
            mma_f16(acc[0], a0, a1, a2, a3, b0, b1);
            mma_f16(acc[1], a0, a1, a2, a3, b2, b3);
            if (do_z) {
                uint32_t bz0, bz1;
                ldsm_x2t(bz0, bz1, vsb + (uint32_t)(((s0 + sB)*CS_VSTR + 32)*2));
                mma_f16(zfrag, a0, a1, a2, a3, bz0, bz1);
            }
        }
        zrun0 += zfrag[0];     // col 32 (valid on lr==0 lanes)
        zrun1 += zfrag[2];
        __syncthreads();
        if (c + 2 < NCHUNK) load_stage(c + 2, st);
    }
    GRID_DEP_LAUNCH();
}

// ---------------------------------------------------------------------------
// Kernel 4: fp16 chunk readout. Register S->A fragments; cp.async staging.
// 2 CTAs/SM (reg-cap experiment reverted: grid size, not resources, bounds occ)
// ---------------------------------------------------------------------------
#define SK_STRH  72
#define SV_STRH  72
#define SKV_STRH 72
#define SK_OFFH  0
#define SV_OFFH  (SK_OFFH + 128*SK_STRH)        // 9216
#define SKV_OFFH (SV_OFFH + 128*SV_STRH)        // 18432
#define CO_HALFS (SKV_OFFH + 64*SKV_STRH)       // 23040
#define CO_SMEM_BYTES (CO_HALFS*2 + 64*4)       // 46336

__global__ __launch_bounds__(256, 2) void chunk_out_f16_kernel()
{
    extern __shared__ __half smh[];
    __half* sk  = smh + SK_OFFH;
    __half* sv  = smh + SV_OFFH;
    __half* skv = smh + SKV_OFFH;
    float*  sz  = (float*)(smh + CO_HALFS);

    GRID_DEP_WAIT();

    const int blk = blockIdx.x;
    const int bh = blk / NCHUNK;
    const int c  = blk % NCHUNK;
    const int tid = threadIdx.x;
    const int wid = tid >> 5;
    const int lane = tid & 31;
    const int lq = lane >> 2;
    const int lr = lane & 3;
    const int wm = wid * 16;

    const size_t base = ((size_t)bh*SEQ + (size_t)c*CHUNK)*DHEAD;

    // Q fragments direct from gmem (issued first; overlap with cp.async below)
    const __half* qp = g_qh + base;
    uint32_t qf[4][4];
#pragma unroll
    for (int s = 0; s < 4; s++) {
        qf[s][0] = *(const uint32_t*)(qp + (wm + lq)*DHEAD     + s*16 + lr*2);
        qf[s][1] = *(const uint32_t*)(qp + (wm + lq + 8)*DHEAD + s*16 + lr*2);
        qf[s][2] = *(const uint32_t*)(qp + (wm + lq)*DHEAD     + s*16 + 8 + lr*2);
        qf[s][3] = *(const uint32_t*)(qp + (wm + lq + 8)*DHEAD + s*16 + 8 + lr*2);
    }

    // cp.async staging: K (1024 x16B), V (1024), kv_pre (512), z_pre (16)
    {
        const __half* kp2 = g_kh + base;
        const __half* vp2 = g_vh + base;
        const __half* kvp = g_kv_preh + (size_t)blk*(DHEAD*DHEAD);
        const float*  zp  = g_z_pre + (size_t)blk*DHEAD;
#pragma unroll
        for (int it = 0; it < 11; it++) {
            int idx = tid + it*256;          // 0..2815 (need 2576)
            if (idx < 1024) {
                int row = idx >> 3, seg = (idx & 7) * 8;
                cp_async16(smem_u32(sk + row*SK_STRH + seg),
                           kp2 + (size_t)row*DHEAD + seg);
            } else if (idx < 2048) {
                int j = idx - 1024;
                int row = j >> 3, seg = (j & 7) * 8;
                cp_async16(smem_u32(sv + row*SV_STRH + seg),
                           vp2 + (size_t)row*DHEAD + seg);
            } else if (idx < 2560) {
                int j = idx - 2048;
                int row = j >> 3, seg = (j & 7) * 8;
                cp_async16(smem_u32(skv + row*SKV_STRH + seg),
                           kvp + (size_t)row*DHEAD + seg);
            } else if (idx < 2576) {
                int j = idx - 2560;          // 0..15 -> 4 floats each
                cp_async16(smem_u32(sz + j*4), zp + j*4);
            }
        }
        cp_commit();
    }
    cp_wait0();
    __syncthreads();

    // ldmatrix addressing
    const int bg   = lane >> 3;
    const int bnt  = (bg >> 1) * 8 + (lane & 7);
    const int bcol = (bg & 1) * 8;
    const int sB = (lane & 7) + ((lane >> 3) & 1) * 8;
    const int nB = ((lane >> 4) & 1) * 8;

    const uint32_t skb  = smem_u32(sk);
    const uint32_t svb  = smem_u32(sv);
    const uint32_t skvb = smem_u32(skv);

    float acc[8][4];
#pragma unroll
    for (int nt = 0; nt < 8; nt++)
#pragma unroll
        for (int i = 0; i < 4; i++) acc[nt][i] = 0.f;

    const int r0 = wm + lq;
    float pnu0 = 0.f, pnu1 = 0.f;

    // ---- intra-chunk causal phase ----
    for (int j = 0; j <= (wm + 15) / 32; j++) {
        const int j32 = j * 32;

        float sfrag[4][4];
#pragma unroll
        for (int nt = 0; nt < 4; nt++)
#pragma unroll
            for (int i = 0; i < 4; i++) sfrag[nt][i] = 0.f;
#pragma unroll
        for (int s = 0; s < 4; s++) {
            uint32_t bf[4][2];
#pragma unroll
            for (int p = 0; p < 2; p++)
                ldsm_x4(bf[2*p][0], bf[2*p][1], bf[2*p+1][0], bf[2*p+1][1],
                        skb + (uint32_t)(((j32 + bnt + p*16)*SK_STRH + s*16 + bcol)*2));
#pragma unroll
            for (int nt = 0; nt < 4; nt++)
                mma_f16(sfrag[nt], qf[s][0], qf[s][1], qf[s][2], qf[s][3],
                        bf[nt][0], bf[nt][1]);
        }
        // mask + nu partials + in-register C->A fragment conversion
        uint32_t aS[2][4];
#pragma unroll
        for (int nt = 0; nt < 4; nt++) {
            int colg = j32 + nt*8 + 2*lr;
            float v00 = (colg   <= r0)   ? sfrag[nt][0] : 0.f;
            float v01 = (colg+1 <= r0)   ? sfrag[nt][1] : 0.f;
            float v10 = (colg   <= r0+8) ? sfrag[nt][2] : 0.f;
            float v11 = (colg+1 <= r0+8) ? sfrag[nt][3] : 0.f;
            pnu0 += v00 + v01;
            pnu1 += v10 + v11;
            aS[nt >> 1][(nt & 1)*2 + 0] = pack_h2(v00, v01);   // row lq
            aS[nt >> 1][(nt & 1)*2 + 1] = pack_h2(v10, v11);   // row lq+8
        }

        // ctx += S (16x32) x V (32x64), B via trans from row-major sv
#pragma unroll
        for (int s = 0; s < 2; s++) {
            const int k0 = j32 + s*16;
            uint32_t bf[8][2];
#pragma unroll
            for (int nn = 0; nn < 4; nn++)
                ldsm_x4t(bf[2*nn][0], bf[2*nn][1], bf[2*nn+1][0], bf[2*nn+1][1],
                         svb + (uint32_t)(((k0 + sB)*SV_STRH + nn*16 + nB)*2));
#pragma unroll
            for (int nt = 0; nt < 8; nt++)
                mma_f16(acc[nt], aS[s][0], aS[s][1], aS[s][2], aS[s][3],
                        bf[nt][0], bf[nt][1]);
        }
    }

    // ---- inter-chunk: ctx += Q x KV_pre ; nu += q . z_pre ----
#pragma unroll
    for (int s = 0; s < 4; s++) {
        const int k0 = s*16;
        uint32_t bf[8][2];
#pragma unroll
        for (int nn = 0; nn < 4; nn++)
            ldsm_x4t(bf[2*nn][0], bf[2*nn][1], bf[2*nn+1][0], bf[2*nn+1][1],
                     skvb + (uint32_t)(((k0 + sB)*SKV_STRH + nn*16 + nB)*2));
#pragma unroll
        for (int nt = 0; nt < 8; nt++)
            mma_f16(acc[nt], qf[s][0], qf[s][1], qf[s][2], qf[s][3],
                    bf[nt][0], bf[nt][1]);
        float2 q0a = __half22float2(*(half2*)&qf[s][0]);
        float2 q1a = __half22float2(*(half2*)&qf[s][1]);
        float2 q0b = __half22float2(*(half2*)&qf[s][2]);
        float2 q1b = __half22float2(*(half2*)&qf[s][3]);
        float z0 = sz[s*16 + 2*lr],     z1 = sz[s*16 + 2*lr + 1];
        float z2 = sz[s*16 + 8 + 2*lr], z3 = sz[s*16 + 8 + 2*lr + 1];
        pnu0 += q0a.x*z0 + q0a.y*z1 + q0b.x*z2 + q0b.y*z3;
        pnu1 += q1a.x*z0 + q1a.y*z1 + q1b.x*z2 + q1b.y*z3;
    }

    pnu0 += __shfl_xor_sync(0xffffffffu, pnu0, 1);
    pnu0 += __shfl_xor_sync(0xffffffffu, pnu0, 2);
    pnu1 += __shfl_xor_sync(0xffffffffu, pnu1, 1);
    pnu1 += __shfl_xor_sync(0xffffffffu, pnu1, 2);
    float inv0 = 1.f / pnu0;
    float inv1 = 1.f / pnu1;

    const int b = bh / NHEAD, h = bh % NHEAD;
    const int s0 = c*CHUNK + r0;
    __half* out0 = g_ctxh + ((size_t)(b*SEQ + s0))*DMODEL + h*DHEAD;
    __half* out1 = g_ctxh + ((size_t)(b*SEQ + s0 + 8))*DMODEL + h*DHEAD;
#pragma unroll
    for (int nt = 0; nt < 8; nt++) {
        int cl = nt*8 + 2*lr;
        *(half2*)(out0 + cl) = __floats2half2_rn(acc[nt][0]*inv0, acc[nt][1]*inv0);
        *(half2*)(out1 + cl) = __floats2half2_rn(acc[nt][2]*inv1, acc[nt][3]*inv1);
    }
    GRID_DEP_LAUNCH();
}

// ---------------------------------------------------------------------------
// Kernel 5: output projection, 64(M)x128(N) tiles, 256 CTAs
// ---------------------------------------------------------------------------
#define OUT_AH (64*ASTRH)
#define OUT_BH (128*ASTRH)
#define OUT_SMEM_BYTES (NSTAGE*(OUT_AH+OUT_BH)*2)   // 55296

__global__ __launch_bounds__(256, 2) void out_f16_gemm(
    const float* __restrict__ bo, float* __restrict__ out)
{
    extern __shared__ __half smh[];
    __half* As = smh;
    __half* Bs = smh + NSTAGE*OUT_AH;

    GRID_DEP_WAIT();

    const int n0 = blockIdx.x * 128;
    const int m0 = blockIdx.y * 64;
    const int tid = threadIdx.x;
    const int wid = tid >> 5;
    const int lane = tid & 31;
    const int warp_m = (wid & 1) * 32;
    const int warp_n = (wid >> 1) * 32;

    float c[2][4][4];
#pragma unroll
    for (int mt = 0; mt < 2; mt++)
#pragma unroll
        for (int nt = 0; nt < 4; nt++)
#pragma unroll
            for (int i = 0; i < 4; i++) c[mt][nt][i] = 0.f;

    auto load_stage = [&](int kt, int stage) {
        const int k0 = kt * KTH;
        __half* Ad = As + stage * OUT_AH;
        __half* Bd = Bs + stage * OUT_BH;
#pragma unroll
        for (int it = 0; it < 6; it++) {
            int i = tid + it*256;
            if (i < 512) {
                int row = i >> 3;
                int seg = (i & 7) * 8;
                cp_async16(smem_u32(Ad + row*ASTRH + seg),
                           g_ctxh + (size_t)(m0 + row)*DMODEL + k0 + seg);
            } else {
                int j = i - 512;
                int row = j >> 3;
                int seg = (j & 7) * 8;
                cp_async16(smem_u32(Bd + row*ASTRH + seg),
                           g_woh + (size_t)(n0 + row)*DMODEL + k0 + seg);
            }
        }
        cp_commit();
    };

    load_stage(0, 0);
    load_stage(1, 1);

    const int arow = warp_m + (lane & 15);
    const int acol = ((lane >> 4) & 1) * 8;
    const int bg   = lane >> 3;
    const int brow = warp_n + (bg >> 1) * 8 + (lane & 7);
    const int bcol = (bg & 1) * 8;

    for (int kt = 0; kt < NKTH; kt++) {
        if (kt < NKTH - 1) cp_wait1(); else cp_wait0();
        __syncthreads();
        int st = kt & 1;
        const uint32_t Ab = smem_u32(As + st*OUT_AH);
        const uint32_t Bb = smem_u32(Bs + st*OUT_BH);
#pragma unroll
        for (int kk = 0; kk < KTH; kk += 16) {
            uint32_t af[2][4];
            uint32_t bf[4][2];
#pragma unroll
            for (int mt = 0; mt < 2; mt++)
                ldsm_x4(af[mt][0], af[mt][1], af[mt][2], af[mt][3],
                        Ab + (uint32_t)(((arow + mt*16)*ASTRH + kk + acol)*2));
#pragma unroll
            for (int p = 0; p < 2; p++)
                ldsm_x4(bf[2*p][0], bf[2*p][1], bf[2*p+1][0], bf[2*p+1][1],
                        Bb + (uint32_t)(((brow + p*16)*ASTRH + kk + bcol)*2));
#pragma unroll
            for (int mt = 0; mt < 2; mt++)
#pragma unroll
                for (int nt = 0; nt < 4; nt++)
                    mma_f16(c[mt][nt], af[mt][0], af[mt][1], af[mt][2], af[mt][3],
                            bf[nt][0], bf[nt][1]);
        }
        if (kt + 2 < NKTH) {
            __syncthreads();
            load_stage(kt + 2, st);
        }
    }

    const int lq = lane >> 2;
    const int lc = (lane & 3) * 2;
#pragma unroll
    for (int mt = 0; mt < 2; mt++) {
#pragma unroll
        for (int rv = 0; rv < 2; rv++) {
            int m = m0 + warp_m + mt*16 + lq + rv*8;
#pragma unroll
            for (int nt = 0; nt < 4; nt++) {
                int nf = n0 + warp_n + nt*8 + lc;
                float v0 = c[mt][nt][rv*2+0] + bo[nf];
                float v1 = c[mt][nt][rv*2+1] + bo[nf+1];
                *(float2*)(out + (size_t)m*DMODEL + nf) = make_float2(v0, v1);
            }
        }
    }
}

// ---------------------------------------------------------------------------
// Host: PDL launcher with plain fallback
// ---------------------------------------------------------------------------
static void launch_pdl(const void* func, dim3 grid, dim3 block, size_t smem,
                       void** args)
{
    cudaLaunchConfig_t cfg = {};
    cfg.gridDim = grid;
    cfg.blockDim = block;
    cfg.dynamicSmemBytes = smem;
    cfg.stream = 0;
    cudaLaunchAttribute attr[1];
    attr[0].id = cudaLaunchAttributeProgrammaticStreamSerialization;
    attr[0].val.programmaticStreamSerializationAllowed = 1;
    cfg.attrs = attr;
    cfg.numAttrs = 1;
    cudaError_t e = cudaLaunchKernelExC(&cfg, func, args);
    if (e != cudaSuccess) {
        cudaGetLastError();  // clear
        cudaLaunchKernel(func, grid, block, args, smem, 0);
    }
}

extern "C" void kernel_launch(void* const* d_in, const int* in_sizes, int n_in,
                              void* d_out, int out_size)
{
    const float* x     = (const float*)d_in[0];
    const float* Wqk_w = (const float*)d_in[1];
    const float* Wqk_b = (const float*)d_in[2];
    const float* Wv_w  = (const float*)d_in[3];
    const float* Wv_b  = (const float*)d_in[4];
    const float* Wo_w  = (const float*)d_in[5];
    const float* Wo_b  = (const float*)d_in[6];
    float* out = (float*)d_out;

    cudaFuncSetAttribute(qkv_f16_gemm,
        cudaFuncAttributeMaxDynamicSharedMemorySize, GEMM_SMEM_BYTES);
    cudaFuncSetAttribute(out_f16_gemm,
        cudaFuncAttributeMaxDynamicSharedMemorySize, OUT_SMEM_BYTES);
    cudaFuncSetAttribute(chunk_out_f16_kernel,
        cudaFuncAttributeMaxDynamicSharedMemorySize, CO_SMEM_BYTES);
    cudaFuncSetAttribute(chunk_state_kernel,
        cudaFuncAttributeMaxDynamicSharedMemorySize, CS_SMEM_BYTES);

    conv_kernel<<<N8_TOT/256, 256>>>((const float4*)x, (const float4*)Wqk_w,
                                     (const float4*)Wv_w, (const float4*)Wo_w);

    {
        void* args[] = { (void*)&Wqk_b, (void*)&Wv_b };
        launch_pdl((const void*)qkv_f16_gemm,
                   dim3(NFEAT/128, NTOK/128), dim3(256), GEMM_SMEM_BYTES, args);
    }
    {
        launch_pdl((const void*)chunk_state_kernel,
                   dim3(BHEADS, 2), dim3(256), CS_SMEM_BYTES, nullptr);
    }
    {
        launch_pdl((const void*)chunk_out_f16_kernel,
                   dim3(BHEADS*NCHUNK), dim3(256), CO_SMEM_BYTES, nullptr);
    }
    {
        void* args[] = { (void*)&Wo_b, (void*)&out };
        launch_pdl((const void*)out_f16_gemm,
                   dim3(DMODEL/128, NTOK/64), dim3(256), OUT_SMEM_BYTES, args);
    }
}